// round 4
// baseline (speedup 1.0000x reference)
#include <cuda_runtime.h>

// ---------------------------------------------------------------------------
// H3 block: Q/K/V proj -> shift-SSM FIR on K -> per-head KV outer product ->
// S4D diagonal SSM (as a linear recurrence scan) -> Q contraction -> out proj.
// B=1, S=1024, D=512, HEADS=8, DH=64, HID(N)=64, CD=32768, DT=0.1
// ---------------------------------------------------------------------------

#define SQ   1024
#define DD   512
#define NH   8
#define DHD  64
#define NST  64

// scratch (device globals: allocation-free rule)
__device__ float g_Q [SQ*DD];
__device__ float g_K0[SQ*DD];
__device__ float g_K [SQ*DD];
__device__ float g_V [SQ*DD];
__device__ float g_Ot[DD*SQ];   // pre-WO output, TRANSPOSED: [d][s]

typedef unsigned long long u64t;

__device__ __forceinline__ u64t pack2(float lo, float hi) {
    u64t r; asm("mov.b64 %0, {%1,%2};" : "=l"(r) : "f"(lo), "f"(hi)); return r;
}
__device__ __forceinline__ void unpack2(u64t v, float& lo, float& hi) {
    asm("mov.b64 {%0,%1}, %2;" : "=f"(lo), "=f"(hi) : "l"(v));
}
// packed 2xFP32 FMA (sm_100+/sm_103a): one instruction, two FMAs
__device__ __forceinline__ u64t fma2(u64t a, u64t b, u64t c) {
    u64t d; asm("fma.rn.f32x2 %0, %1, %2, %3;" : "=l"(d) : "l"(a), "l"(b), "l"(c)); return d;
}
__device__ __forceinline__ u64t mul2(u64t a, u64t b) {
    u64t d; asm("mul.rn.f32x2 %0, %1, %2;" : "=l"(d) : "l"(a), "l"(b)); return d;
}

// ---------------------------------------------------------------------------
// GEMM 1: C[M=1024,N=512] = A[1024,512] @ W[512,512]^T   (x3 via grid.z)
// 64x64 block tile, BK=16, 256 threads, 4x4 register tile per thread.
// ---------------------------------------------------------------------------
__global__ __launch_bounds__(256) void gemm_qkv(
    const float* __restrict__ A,
    const float* __restrict__ WQ, const float* __restrict__ WK,
    const float* __restrict__ WV)
{
    const float* W = (blockIdx.z == 0) ? WQ : (blockIdx.z == 1) ? WK : WV;
    float*       C = (blockIdx.z == 0) ? g_Q : (blockIdx.z == 1) ? g_K0 : g_V;

    __shared__ __align__(16) float As[16][64];
    __shared__ __align__(16) float Bs[16][64];

    const int t  = threadIdx.x;
    const int tx = t & 15, ty = t >> 4;
    const int m0 = blockIdx.y * 64, n0 = blockIdx.x * 64;
    const int lr = t >> 2, lk = (t & 3) * 4;

    float acc[4][4] = {};

    for (int k0 = 0; k0 < 512; k0 += 16) {
        float4 av = *(const float4*)(A + (m0 + lr) * 512 + k0 + lk);
        float4 bv = *(const float4*)(W + (n0 + lr) * 512 + k0 + lk);
        __syncthreads();
        As[lk+0][lr] = av.x; As[lk+1][lr] = av.y; As[lk+2][lr] = av.z; As[lk+3][lr] = av.w;
        Bs[lk+0][lr] = bv.x; Bs[lk+1][lr] = bv.y; Bs[lk+2][lr] = bv.z; Bs[lk+3][lr] = bv.w;
        __syncthreads();
#pragma unroll
        for (int k = 0; k < 16; k++) {
            float4 a4 = *(const float4*)&As[k][ty * 4];
            float4 b4 = *(const float4*)&Bs[k][tx * 4];
            float ar[4] = {a4.x, a4.y, a4.z, a4.w};
            float br[4] = {b4.x, b4.y, b4.z, b4.w};
#pragma unroll
            for (int e = 0; e < 4; e++)
#pragma unroll
                for (int f = 0; f < 4; f++) acc[e][f] += ar[e] * br[f];
        }
    }
#pragma unroll
    for (int e = 0; e < 4; e++) {
        float4 v = make_float4(acc[e][0], acc[e][1], acc[e][2], acc[e][3]);
        *(float4*)(C + (m0 + ty * 4 + e) * 512 + n0 + tx * 4) = v;
    }
}

// ---------------------------------------------------------------------------
// Shift-SSM on K: K[s,d] = sum_{t=0..min(s,63)} C_shift[d,t]*K0[s-t,d]
//                          + D_shift[d]*K0[s,d]
// One block per channel d; taps + column staged in SMEM.
// ---------------------------------------------------------------------------
__global__ __launch_bounds__(256) void shift_conv(
    const float* __restrict__ Cs, const float* __restrict__ Ds)
{
    const int d = blockIdx.x;
    __shared__ float taps[64];
    __shared__ float col[1024];
    const int t = threadIdx.x;
    if (t < 64) taps[t] = Cs[d * 64 + t];
    for (int s = t; s < 1024; s += 256) col[s] = g_K0[s * 512 + d];
    __syncthreads();
    const float dsv = Ds[d];
    for (int s = t; s < 1024; s += 256) {
        float acc = dsv * col[s];
        const int tmax = (s < 63) ? s : 63;
        for (int tt = 0; tt <= tmax; tt++) acc += taps[tt] * col[s - tt];
        g_K[s * 512 + d] = acc;
    }
}

// ---------------------------------------------------------------------------
// S4D diagonal SSM as a fused recurrence scan + Q contraction.
//
// channel c = h*4096 + i*64 + j,  u[c,s] = K[s,h,i] * V[s,h,j]
//   z[n,c,s] = dA[n]*z[n,c,s-1] + u[c,s]          (complex, z[-1]=0)
//   y[c,s]   = 2*Re( sum_n CB[c,n]*z[n,c,s] ) + D_diag[c]*u[c,s]
//   O[s,h,j] = sum_i Q[s,h,i] * y[(h,i,j),s]      -> g_Ot[h*64+j][s]
//
// grid = 512 blocks (h,j); 256 threads: thread = (i = t>>2, n-quarter = t&3).
// 16 complex states/thread kept packed (re/im pairs of adjacent n) in regs;
// all per-step math is packed fma.rn.f32x2. Q/K/V staged in SMEM in 64-step
// chunks. Per-step butterfly shuffles reduce over n-quarters then i.
// ---------------------------------------------------------------------------
__global__ __launch_bounds__(256) void scan_s4d(
    const float* __restrict__ Are, const float* __restrict__ Aim,
    const float* __restrict__ Cre, const float* __restrict__ Cim,
    const float* __restrict__ Dd)
{
    const int bx = blockIdx.x;
    const int h = bx >> 6, j = bx & 63;
    const int t = threadIdx.x;
    const int i = t >> 2, nq = t & 3, n0 = nq * 16;
    const int c = h * 4096 + i * 64 + j;
    const int lane = t & 31, warp = t >> 5;

    u64t dAre2[8], dAim2[8], ndAim2[8], C2re2[8], nC2im2[8], zre2[8], zim2[8];

#pragma unroll
    for (int p = 0; p < 8; p++) {
        float dare[2], daim[2], c2re[2], c2im[2];
#pragma unroll
        for (int e = 0; e < 2; e++) {
            const int n = n0 + 2 * p + e;
            const float are = Are[n], aim = Aim[n];
            // d = 1 - DT*A/2, num = 1 + DT*A/2   (DT/2 = 0.05)
            const float dre = 1.f - 0.05f * are, dim = -0.05f * aim;
            const float nre = 1.f + 0.05f * are, nim = 0.05f * aim;
            const float inv = 1.f / (dre * dre + dim * dim);
            dare[e] = (nre * dre + nim * dim) * inv;       // dA = num/d
            daim[e] = (nim * dre - nre * dim) * inv;
            const float dbre = 0.1f * dre * inv;           // dB = DT/d
            const float dbim = -0.1f * dim * inv;
            const float cr = Cre[c * 64 + n], ci = Cim[c * 64 + n];
            c2re[e] = 2.f * (cr * dbre - ci * dbim);       // 2*CB (fold factor 2)
            c2im[e] = 2.f * (cr * dbim + ci * dbre);
        }
        dAre2[p]  = pack2(dare[0], dare[1]);
        dAim2[p]  = pack2(daim[0], daim[1]);
        ndAim2[p] = pack2(-daim[0], -daim[1]);
        C2re2[p]  = pack2(c2re[0], c2re[1]);
        nC2im2[p] = pack2(-c2im[0], -c2im[1]);
        zre2[p] = 0ull; zim2[p] = 0ull;
    }
    const float ddv = Dd[c];

    __shared__ __align__(16) float Qs[4096];
    __shared__ __align__(16) float Ks[4096];
    __shared__ float Vs[64];
    __shared__ float obuf[512];

    for (int ch = 0; ch < 16; ch++) {
        const int s0 = ch * 64;
        __syncthreads();
        for (int idx = t; idx < 4096; idx += 256) {
            const int r = idx >> 6, cc = idx & 63;
            Qs[idx] = g_Q[(s0 + r) * 512 + h * 64 + cc];
            Ks[idx] = g_K[(s0 + r) * 512 + h * 64 + cc];
        }
        if (t < 64) Vs[t] = g_V[(s0 + t) * 512 + h * 64 + j];
        __syncthreads();

#pragma unroll 2
        for (int r = 0; r < 64; r++) {
            const float u  = Ks[r * 64 + i] * Vs[r];
            const u64t u2  = pack2(u, u);
            u64t acc = 0ull;
#pragma unroll
            for (int p = 0; p < 8; p++) {
                // zre' = dAre*zre - dAim*zim + u ; zim' = dAre*zim + dAim*zre
                const u64t a = fma2(ndAim2[p], zim2[p], u2);
                const u64t b = mul2(dAim2[p], zre2[p]);
                zim2[p] = fma2(dAre2[p], zim2[p], b);
                zre2[p] = fma2(dAre2[p], zre2[p], a);
                // y partial: 2*(CBre*zre - CBim*zim)
                acc = fma2(C2re2[p], zre2[p], acc);
                acc = fma2(nC2im2[p], zim2[p], acc);
            }
            float alo, ahi; unpack2(acc, alo, ahi);
            float yp = alo + ahi;
            // reduce over the 4 n-quarters of channel c
            yp += __shfl_xor_sync(0xffffffffu, yp, 1);
            yp += __shfl_xor_sync(0xffffffffu, yp, 2);
            // y[c] complete -> weight by Q[s,h,i] (+ skip term)
            float val = (yp + ddv * u) * Qs[r * 64 + i];
            // reduce over the 8 i's in this warp
            val += __shfl_xor_sync(0xffffffffu, val, 4);
            val += __shfl_xor_sync(0xffffffffu, val, 8);
            val += __shfl_xor_sync(0xffffffffu, val, 16);
            if (lane == 0) obuf[r * 8 + warp] = val;
        }
        __syncthreads();
        if (t < 64) {
            float o = 0.f;
#pragma unroll
            for (int w = 0; w < 8; w++) o += obuf[t * 8 + w];
            g_Ot[(h * 64 + j) * 1024 + s0 + t] = o;   // coalesced: [d][s]
        }
    }
}

// ---------------------------------------------------------------------------
// GEMM 2: out[s,n] = sum_k g_Ot[k][s] * WO[n,k]   (A is pre-transposed [K,M])
// ---------------------------------------------------------------------------
__global__ __launch_bounds__(256) void gemm_out(
    const float* __restrict__ WO, float* __restrict__ out)
{
    __shared__ __align__(16) float As[16][64];
    __shared__ __align__(16) float Bs[16][64];

    const int t  = threadIdx.x;
    const int tx = t & 15, ty = t >> 4;
    const int m0 = blockIdx.y * 64, n0 = blockIdx.x * 64;
    const int lr = t >> 2, lk = (t & 3) * 4;
    const int kk = t >> 4, mm = (t & 15) * 4;

    float acc[4][4] = {};

    for (int k0 = 0; k0 < 512; k0 += 16) {
        float4 av = *(const float4*)(g_Ot + (k0 + kk) * 1024 + m0 + mm);
        float4 bv = *(const float4*)(WO + (n0 + lr) * 512 + k0 + lk);
        __syncthreads();
        *(float4*)&As[kk][mm] = av;   // already [k][m]
        Bs[lk+0][lr] = bv.x; Bs[lk+1][lr] = bv.y; Bs[lk+2][lr] = bv.z; Bs[lk+3][lr] = bv.w;
        __syncthreads();
#pragma unroll
        for (int k = 0; k < 16; k++) {
            float4 a4 = *(const float4*)&As[k][ty * 4];
            float4 b4 = *(const float4*)&Bs[k][tx * 4];
            float ar[4] = {a4.x, a4.y, a4.z, a4.w};
            float br[4] = {b4.x, b4.y, b4.z, b4.w};
#pragma unroll
            for (int e = 0; e < 4; e++)
#pragma unroll
                for (int f = 0; f < 4; f++) acc[e][f] += ar[e] * br[f];
        }
    }
#pragma unroll
    for (int e = 0; e < 4; e++) {
        float4 v = make_float4(acc[e][0], acc[e][1], acc[e][2], acc[e][3]);
        *(float4*)(out + (m0 + ty * 4 + e) * 512 + n0 + tx * 4) = v;
    }
}

// ---------------------------------------------------------------------------
extern "C" void kernel_launch(void* const* d_in, const int* in_sizes, int n_in,
                              void* d_out, int out_size)
{
    (void)in_sizes; (void)n_in; (void)out_size;
    const float* x   = (const float*)d_in[0];
    const float* WQ  = (const float*)d_in[1];
    const float* WK  = (const float*)d_in[2];
    const float* WV  = (const float*)d_in[3];
    const float* WO  = (const float*)d_in[4];
    const float* Cs  = (const float*)d_in[5];   // C_shift (D, 64)
    const float* Ds  = (const float*)d_in[6];   // D_shift (D,)
    const float* Are = (const float*)d_in[7];
    const float* Aim = (const float*)d_in[8];
    const float* Cre = (const float*)d_in[9];   // (CD, 64)
    const float* Cim = (const float*)d_in[10];  // (CD, 64)
    const float* Ddg = (const float*)d_in[11];  // D_diag (CD,)

    gemm_qkv  <<<dim3(8, 16, 3), 256>>>(x, WQ, WK, WV);
    shift_conv<<<512, 256>>>(Cs, Ds);
    scan_s4d  <<<512, 256>>>(Are, Aim, Cre, Cim, Ddg);
    gemm_out  <<<dim3(8, 16), 256>>>(WO, (float*)d_out);
}